// round 4
// baseline (speedup 1.0000x reference)
#include <cuda_runtime.h>
#include <cstdint>

// Problem constants (fixed by the dataset)
#define NN      100000
#define EE      3200000
#define F_IN    256
#define RR      16
#define DD      128
#define BB      16384
#define EPS     1e-5f

#define SCAN_BLK   1024
#define NSCAN      ((NN + SCAN_BLK - 1) / SCAN_BLK)   // 98

// ---------------- scratch (no allocs allowed) ----------------
__device__ __align__(16) float g_h   [NN * RR];   // x @ W^T
__device__ __align__(16) float g_hagg[NN * RR];   // aggregated GCN output
__device__ int   g_degi  [NN];
__device__ float g_dinv  [NN];
__device__ int   g_rowptr[NN + 1];
__device__ int   g_cursor[NN];
__device__ int   g_csr_src[EE];
__device__ int   g_bsum[128];
__device__ int   g_boff[128];
__device__ float g_stats[2];                      // sum, sumsq

// ---------------- helpers ----------------
__device__ __forceinline__ float warpsum(float v) {
#pragma unroll
    for (int o = 16; o > 0; o >>= 1) v += __shfl_xor_sync(0xFFFFFFFFu, v, o);
    return v;
}

// ---------------- kernels ----------------

// 0) init: degi = 0, stats = 0
__global__ void k_init() {
    int i = blockIdx.x * blockDim.x + threadIdx.x;
    if (i < NN) g_degi[i] = 0;
    if (i < 2)  g_stats[i] = 0.0f;
}

// 1) degree: atomic count of incoming edges at dst
__global__ void k_deg(const int* __restrict__ ei) {
    int e = blockIdx.x * blockDim.x + threadIdx.x;
    if (e < EE) atomicAdd(&g_degi[ei[EE + e]], 1);
}

// 2a) per-block inclusive scan of degrees -> local exclusive + block sums
__global__ void k_scan1() {
    __shared__ int sm[SCAN_BLK];
    int t = threadIdx.x;
    int i = blockIdx.x * SCAN_BLK + t;
    int v = (i < NN) ? g_degi[i] : 0;
    sm[t] = v;
    __syncthreads();
#pragma unroll
    for (int o = 1; o < SCAN_BLK; o <<= 1) {
        int add = (t >= o) ? sm[t - o] : 0;
        __syncthreads();
        sm[t] += add;
        __syncthreads();
    }
    if (i < NN) g_rowptr[i] = sm[t] - v;           // local exclusive
    if (t == SCAN_BLK - 1) g_bsum[blockIdx.x] = sm[t];
}

// 2b) scan the block sums (single block, 128 threads)
__global__ void k_scan2() {
    __shared__ int sm[128];
    int t = threadIdx.x;
    int v = (t < NSCAN) ? g_bsum[t] : 0;
    sm[t] = v;
    __syncthreads();
#pragma unroll
    for (int o = 1; o < 128; o <<= 1) {
        int add = (t >= o) ? sm[t - o] : 0;
        __syncthreads();
        sm[t] += add;
        __syncthreads();
    }
    g_boff[t] = sm[t] - v;                          // exclusive
}

// 2c) finalize rowptr, init cursor, compute dinv (deg includes self-loop)
__global__ void k_scan3() {
    int i = blockIdx.x * blockDim.x + threadIdx.x;
    if (i < NN) {
        int rp = g_rowptr[i] + g_boff[i >> 10];
        g_rowptr[i] = rp;
        g_cursor[i] = rp;
        g_dinv[i]   = rsqrtf((float)(g_degi[i] + 1));
    }
    if (i == 0) g_rowptr[NN] = EE;
}

// 3) fill CSR: slot per edge under its dst
__global__ void k_fill(const int* __restrict__ ei) {
    int e = blockIdx.x * blockDim.x + threadIdx.x;
    if (e >= EE) return;
    int s = ei[e];
    int d = ei[EE + e];
    int pos = atomicAdd(&g_cursor[d], 1);
    g_csr_src[pos] = s;
}

// 4) h = x @ W^T   (one warp per node, W cached in smem)
__global__ void k_lin(const float* __restrict__ x, const float* __restrict__ W) {
    __shared__ float4 Ws[RR * 64];                 // 16 rows x 64 float4 = 16KB
    for (int i = threadIdx.x; i < RR * 64; i += blockDim.x)
        Ws[i] = ((const float4*)W)[i];
    __syncthreads();

    int gwarp  = (blockIdx.x * blockDim.x + threadIdx.x) >> 5;
    int lane   = threadIdx.x & 31;
    int nwarps = (gridDim.x * blockDim.x) >> 5;

    for (int n = gwarp; n < NN; n += nwarps) {
        const float4* xr = (const float4*)(x + (size_t)n * F_IN);
        float4 x0 = xr[lane], x1 = xr[lane + 32];
        float myval = 0.0f;
#pragma unroll
        for (int r = 0; r < RR; r++) {
            float4 w0 = Ws[r * 64 + lane], w1 = Ws[r * 64 + lane + 32];
            float acc = x0.x*w0.x + x0.y*w0.y + x0.z*w0.z + x0.w*w0.w
                      + x1.x*w1.x + x1.y*w1.y + x1.z*w1.z + x1.w*w1.w;
            acc = warpsum(acc);
            if (lane == r) myval = acc;
        }
        if (lane < RR) g_h[(size_t)n * RR + lane] = myval;
    }
}

// 5) gather aggregation: warp per dst node; includes self-loop + bias.
//    hagg[n] = dinv[n] * sum_e dinv[src_e]*h[src_e] + dinv[n]^2*h[n] + b
//    NOTE: trip count rounded up to even so both warp-halves stay converged
//    through the full-mask shuffles (odd cnt previously deadlocked).
__global__ void k_agg(const float* __restrict__ bias) {
    int gwarp = (blockIdx.x * blockDim.x + threadIdx.x) >> 5;
    if (gwarp >= NN) return;
    int n    = gwarp;
    int lane = threadIdx.x & 31;
    int ch   = lane & 15;
    int half = lane >> 4;

    int start = g_rowptr[n];
    int end   = g_rowptr[n + 1];

    float acc = 0.0f;
    for (int base = start; base < end; base += 32) {
        int idx = base + lane;
        int cnt = min(32, end - base);
        int cnt2 = (cnt + 1) & ~1;                 // even => uniform trip count
        int   s  = 0;
        float ws = 0.0f;
        if (idx < end) {
            s  = g_csr_src[idx];
            ws = __ldg(&g_dinv[s]);
        }
        for (int j = half; j < cnt2; j += 2) {
            int   se = __shfl_sync(0xFFFFFFFFu, s,  j);
            float we = __shfl_sync(0xFFFFFFFFu, ws, j);
            if (j < cnt)
                acc += we * __ldg(&g_h[(size_t)se * RR + ch]);
        }
    }
    acc += __shfl_xor_sync(0xFFFFFFFFu, acc, 16);

    if (lane < 16) {
        float d    = g_dinv[n];
        float self = g_h[(size_t)n * RR + ch];
        g_hagg[(size_t)n * RR + ch] = d * acc + d * d * self + bias[ch];
    }
}

// 6) global LN stats: sum + sumsq over all NN*RR elements
__global__ void k_stats() {
    const float4* p = (const float4*)g_hagg;
    const int total = NN * RR / 4;
    float s = 0.0f, q = 0.0f;
    for (int i = blockIdx.x * blockDim.x + threadIdx.x; i < total;
         i += gridDim.x * blockDim.x) {
        float4 v = p[i];
        s += v.x + v.y + v.z + v.w;
        q += v.x*v.x + v.y*v.y + v.z*v.z + v.w*v.w;
    }
    s = warpsum(s); q = warpsum(q);
    __shared__ float ss[32], qq[32];
    int lane = threadIdx.x & 31, wid = threadIdx.x >> 5;
    if (lane == 0) { ss[wid] = s; qq[wid] = q; }
    __syncthreads();
    if (wid == 0) {
        int nw = blockDim.x >> 5;
        s = lane < nw ? ss[lane] : 0.0f;
        q = lane < nw ? qq[lane] : 0.0f;
        s = warpsum(s); q = warpsum(q);
        if (lane == 0) { atomicAdd(&g_stats[0], s); atomicAdd(&g_stats[1], q); }
    }
}

// 7) output: per batch row, LN + PReLU + @trans. 8 rows per 128-thread block.
__global__ void k_out(const float* __restrict__ trans,
                      const int* __restrict__ batch,
                      const float* __restrict__ lnw,
                      const float* __restrict__ lnb,
                      const float* __restrict__ pa,
                      float* __restrict__ out) {
    __shared__ float ts[RR * DD];                  // 8KB
    __shared__ float hv[8][RR];
    for (int i = threadIdx.x; i < RR * DD; i += blockDim.x)
        ts[i] = trans[i];

    const float inv = 1.0f / (float)(NN * RR);
    float mean = g_stats[0] * inv;
    float var  = g_stats[1] * inv - mean * mean;
    float rinv = rsqrtf(var + EPS);
    float a    = pa[0];

    int row0 = blockIdx.x * 8;
    {   // 128 threads = 8 rows x 16 channels, exactly
        int row = threadIdx.x >> 4, r = threadIdx.x & 15;
        int bi = batch[row0 + row];
        float v = g_hagg[(size_t)bi * RR + r];
        v = (v - mean) * rinv * lnw[r] + lnb[r];
        v = v >= 0.0f ? v : a * v;
        hv[row][r] = v;
    }
    __syncthreads();

#pragma unroll
    for (int row = 0; row < 8; row++) {
        float acc = 0.0f;
#pragma unroll
        for (int k = 0; k < RR; k++)
            acc += hv[row][k] * ts[k * DD + threadIdx.x];
        out[(size_t)(row0 + row) * DD + threadIdx.x] = acc;
    }
}

// ---------------- launch ----------------
extern "C" void kernel_launch(void* const* d_in, const int* in_sizes, int n_in,
                              void* d_out, int out_size) {
    const float* x     = (const float*)d_in[0];
    const int*   ei    = (const int*)d_in[1];
    const float* trans = (const float*)d_in[2];
    const int*   batch = (const int*)d_in[3];
    const float* W     = (const float*)d_in[4];
    const float* bias  = (const float*)d_in[5];
    const float* lnw   = (const float*)d_in[6];
    const float* lnb   = (const float*)d_in[7];
    const float* pa    = (const float*)d_in[8];
    float* out = (float*)d_out;

    k_init <<<(NN + 255) / 256, 256>>>();
    k_deg  <<<(EE + 255) / 256, 256>>>(ei);
    k_scan1<<<NSCAN, SCAN_BLK>>>();
    k_scan2<<<1, 128>>>();
    k_scan3<<<(NN + 255) / 256, 256>>>();
    k_fill <<<(EE + 255) / 256, 256>>>(ei);
    k_lin  <<<(NN + 7) / 8, 256>>>(x, W);          // 8 warps/block, 1 node/warp
    k_agg  <<<(NN * 32 + 255) / 256, 256>>>(bias); // 1 warp/node
    k_stats<<<1024, 256>>>();
    k_out  <<<BB / 8, 128>>>(trans, batch, lnw, lnb, pa, out);
}

// round 5
// speedup vs baseline: 1.0019x; 1.0019x over previous
#include <cuda_runtime.h>
#include <cstdint>

// Problem constants (fixed by the dataset)
#define NN      100000
#define EE      3200000
#define F_IN    256
#define RR      16
#define DD      128
#define BB      16384
#define EPS     1e-5f

#define SCAN_BLK   1024
#define NSCAN      ((NN + SCAN_BLK - 1) / SCAN_BLK)   // 98

// ---------------- scratch (no allocs allowed) ----------------
__device__ __align__(16) float g_h   [NN * RR];   // x @ W^T
__device__ __align__(16) float g_hagg[NN * RR];   // aggregated GCN output
__device__ int   g_degi  [NN];
__device__ float g_dinv  [NN];
__device__ int   g_rowptr[NN + 1];
__device__ int   g_cursor[NN];
__device__ int   g_csr_src[EE];
__device__ int   g_bsum[128];
__device__ int   g_boff[128];
__device__ float g_stats[2];                      // sum, sumsq

// ---------------- helpers ----------------
__device__ __forceinline__ float warpsum(float v) {
#pragma unroll
    for (int o = 16; o > 0; o >>= 1) v += __shfl_xor_sync(0xFFFFFFFFu, v, o);
    return v;
}

// butterfly-sum within each 16-lane half (offsets 1,2,4,8 never cross halves)
__device__ __forceinline__ float red16(float v) {
#pragma unroll
    for (int o = 1; o < 16; o <<= 1) v += __shfl_xor_sync(0xFFFFFFFFu, v, o);
    return v;
}

// ---------------- kernels ----------------

// 0) init: degi = 0, stats = 0
__global__ void k_init() {
    int i = blockIdx.x * blockDim.x + threadIdx.x;
    if (i < NN) g_degi[i] = 0;
    if (i < 2)  g_stats[i] = 0.0f;
}

// 1) degree: atomic count of incoming edges at dst
__global__ void k_deg(const int* __restrict__ ei) {
    int e = blockIdx.x * blockDim.x + threadIdx.x;
    if (e < EE) atomicAdd(&g_degi[ei[EE + e]], 1);
}

// 2a) per-block inclusive scan of degrees -> local exclusive + block sums
__global__ void k_scan1() {
    __shared__ int sm[SCAN_BLK];
    int t = threadIdx.x;
    int i = blockIdx.x * SCAN_BLK + t;
    int v = (i < NN) ? g_degi[i] : 0;
    sm[t] = v;
    __syncthreads();
#pragma unroll
    for (int o = 1; o < SCAN_BLK; o <<= 1) {
        int add = (t >= o) ? sm[t - o] : 0;
        __syncthreads();
        sm[t] += add;
        __syncthreads();
    }
    if (i < NN) g_rowptr[i] = sm[t] - v;           // local exclusive
    if (t == SCAN_BLK - 1) g_bsum[blockIdx.x] = sm[t];
}

// 2b) scan the block sums (single block, 128 threads)
__global__ void k_scan2() {
    __shared__ int sm[128];
    int t = threadIdx.x;
    int v = (t < NSCAN) ? g_bsum[t] : 0;
    sm[t] = v;
    __syncthreads();
#pragma unroll
    for (int o = 1; o < 128; o <<= 1) {
        int add = (t >= o) ? sm[t - o] : 0;
        __syncthreads();
        sm[t] += add;
        __syncthreads();
    }
    g_boff[t] = sm[t] - v;                          // exclusive
}

// 2c) finalize rowptr, init cursor, compute dinv (deg includes self-loop)
__global__ void k_scan3() {
    int i = blockIdx.x * blockDim.x + threadIdx.x;
    if (i < NN) {
        int rp = g_rowptr[i] + g_boff[i >> 10];
        g_rowptr[i] = rp;
        g_cursor[i] = rp;
        g_dinv[i]   = rsqrtf((float)(g_degi[i] + 1));
    }
    if (i == 0) g_rowptr[NN] = EE;
}

// 3) fill CSR: slot per edge under its dst
__global__ void k_fill(const int* __restrict__ ei) {
    int e = blockIdx.x * blockDim.x + threadIdx.x;
    if (e >= EE) return;
    int s = ei[e];
    int d = ei[EE + e];
    int pos = atomicAdd(&g_cursor[d], 1);
    g_csr_src[pos] = s;
}

// 4) h = x @ W^T   (one warp per node, W cached in smem)
__global__ void k_lin(const float* __restrict__ x, const float* __restrict__ W) {
    __shared__ float4 Ws[RR * 64];                 // 16 rows x 64 float4 = 16KB
    for (int i = threadIdx.x; i < RR * 64; i += blockDim.x)
        Ws[i] = ((const float4*)W)[i];
    __syncthreads();

    int gwarp  = (blockIdx.x * blockDim.x + threadIdx.x) >> 5;
    int lane   = threadIdx.x & 31;
    int nwarps = (gridDim.x * blockDim.x) >> 5;

    for (int n = gwarp; n < NN; n += nwarps) {
        const float4* xr = (const float4*)(x + (size_t)n * F_IN);
        float4 x0 = xr[lane], x1 = xr[lane + 32];
        float myval = 0.0f;
#pragma unroll
        for (int r = 0; r < RR; r++) {
            float4 w0 = Ws[r * 64 + lane], w1 = Ws[r * 64 + lane + 32];
            float acc = x0.x*w0.x + x0.y*w0.y + x0.z*w0.z + x0.w*w0.w
                      + x1.x*w1.x + x1.y*w1.y + x1.z*w1.z + x1.w*w1.w;
            acc = warpsum(acc);
            if (lane == r) myval = acc;
        }
        if (lane < RR) g_h[(size_t)n * RR + lane] = myval;
    }
}

// 5) gather aggregation: HALF-WARP (16 lanes) per dst node, one edge per lane.
//    Each lane gathers the full 16-channel row (4x LDG.128) and accumulates
//    into private float4 regs. NO intra-loop shuffles/syncs -> halves may
//    diverge freely. One butterfly reduction per node at the end.
//    hagg[n] = dinv[n] * sum_e dinv[src_e]*h[src_e] + dinv[n]^2*h[n] + b
__global__ void k_agg(const float* __restrict__ bias) {
    int gwarp = (blockIdx.x * blockDim.x + threadIdx.x) >> 5;
    int lane  = threadIdx.x & 31;
    int half  = lane >> 4;        // 0 or 1
    int l16   = lane & 15;
    int n     = gwarp * 2 + half; // node for this half-warp
    if (gwarp * 2 >= NN) return;
    bool valid = (n < NN);

    const float4* __restrict__ h4 = (const float4*)g_h;

    float4 a0 = {0,0,0,0}, a1 = {0,0,0,0}, a2 = {0,0,0,0}, a3 = {0,0,0,0};

    if (valid) {
        int start = g_rowptr[n];
        int end   = g_rowptr[n + 1];
        for (int idx = start + l16; idx < end; idx += 16) {
            int   s = __ldg(&g_csr_src[idx]);
            float w = __ldg(&g_dinv[s]);
            float4 v0 = __ldg(&h4[(size_t)s * 4 + 0]);
            float4 v1 = __ldg(&h4[(size_t)s * 4 + 1]);
            float4 v2 = __ldg(&h4[(size_t)s * 4 + 2]);
            float4 v3 = __ldg(&h4[(size_t)s * 4 + 3]);
            a0.x += w*v0.x; a0.y += w*v0.y; a0.z += w*v0.z; a0.w += w*v0.w;
            a1.x += w*v1.x; a1.y += w*v1.y; a1.z += w*v1.z; a1.w += w*v1.w;
            a2.x += w*v2.x; a2.y += w*v2.y; a2.z += w*v2.z; a2.w += w*v2.w;
            a3.x += w*v3.x; a3.y += w*v3.y; a3.z += w*v3.z; a3.w += w*v3.w;
        }
    }

    // reduce across the 16 lanes of each half (all 32 lanes converged here)
    a0.x = red16(a0.x); a0.y = red16(a0.y); a0.z = red16(a0.z); a0.w = red16(a0.w);
    a1.x = red16(a1.x); a1.y = red16(a1.y); a1.z = red16(a1.z); a1.w = red16(a1.w);
    a2.x = red16(a2.x); a2.y = red16(a2.y); a2.z = red16(a2.z); a2.w = red16(a2.w);
    a3.x = red16(a3.x); a3.y = red16(a3.y); a3.z = red16(a3.z); a3.w = red16(a3.w);

    if (valid && l16 < 4) {
        float4 v = a0;
        if (l16 == 1) v = a1;
        else if (l16 == 2) v = a2;
        else if (l16 == 3) v = a3;
        float  d    = g_dinv[n];
        float4 self = h4[(size_t)n * 4 + l16];
        float4 bs   = ((const float4*)bias)[l16];
        float  dd   = d * d;
        v.x = d*v.x + dd*self.x + bs.x;
        v.y = d*v.y + dd*self.y + bs.y;
        v.z = d*v.z + dd*self.z + bs.z;
        v.w = d*v.w + dd*self.w + bs.w;
        ((float4*)g_hagg)[(size_t)n * 4 + l16] = v;
    }
}

// 6) global LN stats: sum + sumsq over all NN*RR elements
__global__ void k_stats() {
    const float4* p = (const float4*)g_hagg;
    const int total = NN * RR / 4;
    float s = 0.0f, q = 0.0f;
    for (int i = blockIdx.x * blockDim.x + threadIdx.x; i < total;
         i += gridDim.x * blockDim.x) {
        float4 v = p[i];
        s += v.x + v.y + v.z + v.w;
        q += v.x*v.x + v.y*v.y + v.z*v.z + v.w*v.w;
    }
    s = warpsum(s); q = warpsum(q);
    __shared__ float ss[32], qq[32];
    int lane = threadIdx.x & 31, wid = threadIdx.x >> 5;
    if (lane == 0) { ss[wid] = s; qq[wid] = q; }
    __syncthreads();
    if (wid == 0) {
        int nw = blockDim.x >> 5;
        s = lane < nw ? ss[lane] : 0.0f;
        q = lane < nw ? qq[lane] : 0.0f;
        s = warpsum(s); q = warpsum(q);
        if (lane == 0) { atomicAdd(&g_stats[0], s); atomicAdd(&g_stats[1], q); }
    }
}

// 7) output: per batch row, LN + PReLU + @trans. 8 rows per 128-thread block.
__global__ void k_out(const float* __restrict__ trans,
                      const int* __restrict__ batch,
                      const float* __restrict__ lnw,
                      const float* __restrict__ lnb,
                      const float* __restrict__ pa,
                      float* __restrict__ out) {
    __shared__ float ts[RR * DD];                  // 8KB
    __shared__ float hv[8][RR];
    for (int i = threadIdx.x; i < RR * DD; i += blockDim.x)
        ts[i] = trans[i];

    const float inv = 1.0f / (float)(NN * RR);
    float mean = g_stats[0] * inv;
    float var  = g_stats[1] * inv - mean * mean;
    float rinv = rsqrtf(var + EPS);
    float a    = pa[0];

    int row0 = blockIdx.x * 8;
    {   // 128 threads = 8 rows x 16 channels, exactly
        int row = threadIdx.x >> 4, r = threadIdx.x & 15;
        int bi = batch[row0 + row];
        float v = g_hagg[(size_t)bi * RR + r];
        v = (v - mean) * rinv * lnw[r] + lnb[r];
        v = v >= 0.0f ? v : a * v;
        hv[row][r] = v;
    }
    __syncthreads();

#pragma unroll
    for (int row = 0; row < 8; row++) {
        float acc = 0.0f;
#pragma unroll
        for (int k = 0; k < RR; k++)
            acc += hv[row][k] * ts[k * DD + threadIdx.x];
        out[(size_t)(row0 + row) * DD + threadIdx.x] = acc;
    }
}

// ---------------- launch ----------------
extern "C" void kernel_launch(void* const* d_in, const int* in_sizes, int n_in,
                              void* d_out, int out_size) {
    const float* x     = (const float*)d_in[0];
    const int*   ei    = (const int*)d_in[1];
    const float* trans = (const float*)d_in[2];
    const int*   batch = (const int*)d_in[3];
    const float* W     = (const float*)d_in[4];
    const float* bias  = (const float*)d_in[5];
    const float* lnw   = (const float*)d_in[6];
    const float* lnb   = (const float*)d_in[7];
    const float* pa    = (const float*)d_in[8];
    float* out = (float*)d_out;

    k_init <<<(NN + 255) / 256, 256>>>();
    k_deg  <<<(EE + 255) / 256, 256>>>(ei);
    k_scan1<<<NSCAN, SCAN_BLK>>>();
    k_scan2<<<1, 128>>>();
    k_scan3<<<(NN + 255) / 256, 256>>>();
    k_fill <<<(EE + 255) / 256, 256>>>(ei);
    k_lin  <<<(NN + 7) / 8, 256>>>(x, W);              // 8 warps/block, 1 node/warp
    int nwarps_agg = (NN + 1) / 2;                     // 2 nodes per warp
    k_agg  <<<(nwarps_agg * 32 + 255) / 256, 256>>>(bias);
    k_stats<<<1024, 256>>>();
    k_out  <<<BB / 8, 128>>>(trans, batch, lnw, lnb, pa, out);
}

// round 6
// speedup vs baseline: 1.0621x; 1.0600x over previous
#include <cuda_runtime.h>
#include <cstdint>

// Problem constants (fixed by the dataset)
#define NN      100000
#define EE      3200000
#define F_IN    256
#define RR      16
#define DD      128
#define BB      16384
#define EPS     1e-5f

#define SCAN_BLK   1024
#define NSCAN      ((NN + SCAN_BLK - 1) / SCAN_BLK)   // 98

// ---------------- scratch (no allocs allowed) ----------------
__device__ __align__(16) float g_h   [NN * RR];   // x @ W^T
__device__ __align__(16) float g_hagg[NN * RR];   // aggregated GCN output
__device__ int   g_degi  [NN];
__device__ float g_dinv  [NN];
__device__ int   g_rowptr[NN + 1];
__device__ int   g_cursor[NN];
__device__ __align__(16) int2 g_csr[EE];          // {src, bits(dinv[src])}
__device__ int   g_bsum[128];
__device__ int   g_boff[128];
__device__ float g_stats[2];                      // sum, sumsq

// ---------------- helpers ----------------
__device__ __forceinline__ float warpsum(float v) {
#pragma unroll
    for (int o = 16; o > 0; o >>= 1) v += __shfl_xor_sync(0xFFFFFFFFu, v, o);
    return v;
}

// ---------------- kernels ----------------

// 0) init: degi = 0, stats = 0
__global__ void k_init() {
    int i = blockIdx.x * blockDim.x + threadIdx.x;
    if (i < NN) g_degi[i] = 0;
    if (i < 2)  g_stats[i] = 0.0f;
}

// 1) degree: atomic count of incoming edges at dst
__global__ void k_deg(const int* __restrict__ ei) {
    int e = blockIdx.x * blockDim.x + threadIdx.x;
    if (e < EE) atomicAdd(&g_degi[ei[EE + e]], 1);
}

// 2a) per-block inclusive scan of degrees -> local exclusive + block sums
__global__ void k_scan1() {
    __shared__ int sm[SCAN_BLK];
    int t = threadIdx.x;
    int i = blockIdx.x * SCAN_BLK + t;
    int v = (i < NN) ? g_degi[i] : 0;
    sm[t] = v;
    __syncthreads();
#pragma unroll
    for (int o = 1; o < SCAN_BLK; o <<= 1) {
        int add = (t >= o) ? sm[t - o] : 0;
        __syncthreads();
        sm[t] += add;
        __syncthreads();
    }
    if (i < NN) g_rowptr[i] = sm[t] - v;           // local exclusive
    if (t == SCAN_BLK - 1) g_bsum[blockIdx.x] = sm[t];
}

// 2b) scan the block sums (single block, 128 threads)
__global__ void k_scan2() {
    __shared__ int sm[128];
    int t = threadIdx.x;
    int v = (t < NSCAN) ? g_bsum[t] : 0;
    sm[t] = v;
    __syncthreads();
#pragma unroll
    for (int o = 1; o < 128; o <<= 1) {
        int add = (t >= o) ? sm[t - o] : 0;
        __syncthreads();
        sm[t] += add;
        __syncthreads();
    }
    g_boff[t] = sm[t] - v;                          // exclusive
}

// 2c) finalize rowptr, init cursor, compute dinv (deg includes self-loop)
__global__ void k_scan3() {
    int i = blockIdx.x * blockDim.x + threadIdx.x;
    if (i < NN) {
        int rp = g_rowptr[i] + g_boff[i >> 10];
        g_rowptr[i] = rp;
        g_cursor[i] = rp;
        g_dinv[i]   = rsqrtf((float)(g_degi[i] + 1));
    }
    if (i == 0) g_rowptr[NN] = EE;
}

// 3) fill CSR: slot per edge under its dst; pack (src, dinv[src])
__global__ void k_fill(const int* __restrict__ ei) {
    int e = blockIdx.x * blockDim.x + threadIdx.x;
    if (e >= EE) return;
    int s = ei[e];
    int d = ei[EE + e];
    float w = __ldg(&g_dinv[s]);
    int pos = atomicAdd(&g_cursor[d], 1);
    g_csr[pos] = make_int2(s, __float_as_int(w));
}

// 4) h = x @ W^T   (one warp per node, W cached in smem)
__global__ void k_lin(const float* __restrict__ x, const float* __restrict__ W) {
    __shared__ float4 Ws[RR * 64];                 // 16 rows x 64 float4 = 16KB
    for (int i = threadIdx.x; i < RR * 64; i += blockDim.x)
        Ws[i] = ((const float4*)W)[i];
    __syncthreads();

    int gwarp  = (blockIdx.x * blockDim.x + threadIdx.x) >> 5;
    int lane   = threadIdx.x & 31;
    int nwarps = (gridDim.x * blockDim.x) >> 5;

    for (int n = gwarp; n < NN; n += nwarps) {
        const float4* xr = (const float4*)(x + (size_t)n * F_IN);
        float4 x0 = xr[lane], x1 = xr[lane + 32];
        float myval = 0.0f;
#pragma unroll
        for (int r = 0; r < RR; r++) {
            float4 w0 = Ws[r * 64 + lane], w1 = Ws[r * 64 + lane + 32];
            float acc = x0.x*w0.x + x0.y*w0.y + x0.z*w0.z + x0.w*w0.w
                      + x1.x*w1.x + x1.y*w1.y + x1.z*w1.z + x1.w*w1.w;
            acc = warpsum(acc);
            if (lane == r) myval = acc;
        }
        if (lane < RR) g_h[(size_t)n * RR + lane] = myval;
    }
}

// 5) gather aggregation + fused LN stats.
//    ONE WARP per node, channel-per-lane: lanes 0-15 = 16 channels of edge j,
//    lanes 16-31 = 16 channels of edge j+1. Uniform loop bound per warp (no
//    divergence), no shuffles in the loop, csr pair read as one LDG.64 line.
//    hagg[n] = dinv[n]*sum_e(w_e*h[src_e]) + dinv[n]^2*h[n] + b
//    Block = 8 warps = 8 nodes; grid = 12500 blocks = exactly 100000 nodes.
__global__ void k_agg(const float* __restrict__ bias) {
    __shared__ float bs_s[8], bs_q[8];
    int wid  = threadIdx.x >> 5;
    int lane = threadIdx.x & 31;
    int half = lane >> 4;
    int ch   = lane & 15;
    int n    = blockIdx.x * 8 + wid;               // always < NN

    int start = g_rowptr[n];
    int end   = g_rowptr[n + 1];

    const int2* __restrict__ csr = g_csr;
    float acc = 0.0f;

    int j = start + half;                           // this lane's edge stream
    // unrolled x2 for MLP: two independent pairs in flight
    for (; j + 2 < end; j += 4) {
        int2 e0 = __ldg(&csr[j]);
        int2 e1 = __ldg(&csr[j + 2]);
        float w0 = __int_as_float(e0.y);
        float w1 = __int_as_float(e1.y);
        float h0 = __ldg(&g_h[(size_t)e0.x * RR + ch]);
        float h1 = __ldg(&g_h[(size_t)e1.x * RR + ch]);
        acc += w0 * h0;
        acc += w1 * h1;
    }
    for (; j < end; j += 2) {
        int2 e0 = __ldg(&csr[j]);
        acc += __int_as_float(e0.y) * __ldg(&g_h[(size_t)e0.x * RR + ch]);
    }

    // fold the two half-warps (same ch in lane and lane+16)
    acc += __shfl_xor_sync(0xFFFFFFFFu, acc, 16);

    float v = 0.0f;
    if (lane < 16) {
        float d    = g_dinv[n];
        float self = g_h[(size_t)n * RR + ch];
        v = d * acc + d * d * self + bias[ch];
        g_hagg[(size_t)n * RR + ch] = v;
    }

    // fused global-LN stats: block reduce of sum & sumsq
    float s = warpsum(v);                           // lanes>=16 contribute 0
    float q = warpsum(v * v);
    if (lane == 0) { bs_s[wid] = s; bs_q[wid] = q; }
    __syncthreads();
    if (threadIdx.x == 0) {
        float ts = 0.0f, tq = 0.0f;
#pragma unroll
        for (int i = 0; i < 8; i++) { ts += bs_s[i]; tq += bs_q[i]; }
        atomicAdd(&g_stats[0], ts);
        atomicAdd(&g_stats[1], tq);
    }
}

// 6) output: per batch row, LN + PReLU + @trans. 8 rows per 128-thread block.
__global__ void k_out(const float* __restrict__ trans,
                      const int* __restrict__ batch,
                      const float* __restrict__ lnw,
                      const float* __restrict__ lnb,
                      const float* __restrict__ pa,
                      float* __restrict__ out) {
    __shared__ float ts[RR * DD];                  // 8KB
    __shared__ float hv[8][RR];
    for (int i = threadIdx.x; i < RR * DD; i += blockDim.x)
        ts[i] = trans[i];

    const float inv = 1.0f / (float)(NN * RR);
    float mean = g_stats[0] * inv;
    float var  = g_stats[1] * inv - mean * mean;
    float rinv = rsqrtf(var + EPS);
    float a    = pa[0];

    int row0 = blockIdx.x * 8;
    {   // 128 threads = 8 rows x 16 channels, exactly
        int row = threadIdx.x >> 4, r = threadIdx.x & 15;
        int bi = batch[row0 + row];
        float v = g_hagg[(size_t)bi * RR + r];
        v = (v - mean) * rinv * lnw[r] + lnb[r];
        v = v >= 0.0f ? v : a * v;
        hv[row][r] = v;
    }
    __syncthreads();

#pragma unroll
    for (int row = 0; row < 8; row++) {
        float acc = 0.0f;
#pragma unroll
        for (int k = 0; k < RR; k++)
            acc += hv[row][k] * ts[k * DD + threadIdx.x];
        out[(size_t)(row0 + row) * DD + threadIdx.x] = acc;
    }
}

// ---------------- launch ----------------
extern "C" void kernel_launch(void* const* d_in, const int* in_sizes, int n_in,
                              void* d_out, int out_size) {
    const float* x     = (const float*)d_in[0];
    const int*   ei    = (const int*)d_in[1];
    const float* trans = (const float*)d_in[2];
    const int*   batch = (const int*)d_in[3];
    const float* W     = (const float*)d_in[4];
    const float* bias  = (const float*)d_in[5];
    const float* lnw   = (const float*)d_in[6];
    const float* lnb   = (const float*)d_in[7];
    const float* pa    = (const float*)d_in[8];
    float* out = (float*)d_out;

    k_init <<<(NN + 255) / 256, 256>>>();
    k_deg  <<<(EE + 255) / 256, 256>>>(ei);
    k_scan1<<<NSCAN, SCAN_BLK>>>();
    k_lin  <<<(NN + 7) / 8, 256>>>(x, W);          // 4th launch -> ncu profiles this
    k_scan2<<<1, 128>>>();
    k_scan3<<<(NN + 255) / 256, 256>>>();
    k_fill <<<(EE + 255) / 256, 256>>>(ei);
    k_agg  <<<NN / 8, 256>>>(bias);                // 12500 blocks x 8 nodes, exact
    k_out  <<<BB / 8, 128>>>(trans, batch, lnw, lnb, pa, out);
}